// round 6
// baseline (speedup 1.0000x reference)
#include <cuda_runtime.h>
#include <cstdint>

#define TOKENS 32768
#define HID 768
#define INTR 3072
#define NTAGS 64

// ---------------------------------------------------------------------------
// Scratch (static device memory — allocation-free per harness rules)
// ---------------------------------------------------------------------------
__device__ __align__(256) float g_x[(size_t)TOKENS * HID];    // LN1 out (tf32-rounded)
__device__ __align__(256) float g_ffx[(size_t)TOKENS * HID];  // ff + x
__device__ __align__(256) float g_h[(size_t)TOKENS * INTR];   // relu(x@W1+b1) (tf32)
__device__ __align__(256) float g_w1r[HID * INTR];            // tf32-rounded W1 [K,N]
__device__ __align__(256) float g_w2r[INTR * HID];            // tf32-rounded W2 [K,N]
__device__ __align__(256) float g_tmp[NTAGS * HID];
__device__ __align__(256) float g_ptag[NTAGS * HID];

// ---------------------------------------------------------------------------
// Helpers
// ---------------------------------------------------------------------------
__device__ __forceinline__ float tf32r(float x) {
    uint32_t u;
    asm("cvt.rna.tf32.f32 %0, %1;" : "=r"(u) : "f"(x));
    return __uint_as_float(u);
}

__device__ __forceinline__ void cp_async16(uint32_t saddr, const void* gaddr) {
    asm volatile("cp.async.cg.shared.global [%0], [%1], 16;" :: "r"(saddr), "l"(gaddr));
}
__device__ __forceinline__ void cp_commit() { asm volatile("cp.async.commit_group;"); }
template<int N> __device__ __forceinline__ void cp_wait() {
    asm volatile("cp.async.wait_group %0;" :: "n"(N));
}

__device__ __forceinline__ void mma_tf32(float c[4], const uint32_t a[4], const uint32_t b[2]) {
    asm volatile(
        "mma.sync.aligned.m16n8k8.row.col.f32.tf32.tf32.f32 "
        "{%0,%1,%2,%3}, {%4,%5,%6,%7}, {%8,%9}, {%0,%1,%2,%3};"
        : "+f"(c[0]), "+f"(c[1]), "+f"(c[2]), "+f"(c[3])
        : "r"(a[0]), "r"(a[1]), "r"(a[2]), "r"(a[3]), "r"(b[0]), "r"(b[1]));
}

// ---------------------------------------------------------------------------
// Weight rounding: g_w{1,2}r = round_rna_tf32(W)   (layout unchanged: [K,N])
// ---------------------------------------------------------------------------
template<int W>
__global__ void round_w_kernel(const float* __restrict__ in) {
    float* out = W ? g_w2r : g_w1r;
    int i = blockIdx.x * blockDim.x + threadIdx.x;
    const int n = HID * INTR;
    if (i < n) out[i] = tf32r(in[i]);
}

// ---------------------------------------------------------------------------
// per-tag precompute, parallelized: grid (NTAGS, HID/256), 1 output/thread.
// STAGE 0: g_tmp = tag_emb@Wv+bv;  STAGE 1: g_ptag = g_tmp@Wo+bo
// ---------------------------------------------------------------------------
template<int STAGE>
__global__ void __launch_bounds__(256)
tag_gemm_kernel(const float* __restrict__ Eparam, const float* __restrict__ W,
                const float* __restrict__ bias) {
    __shared__ float se[HID];
    const float* E = STAGE ? g_tmp : Eparam;
    float* O = STAGE ? g_ptag : g_tmp;
    int t = blockIdx.x;
    int n = blockIdx.y * 256 + threadIdx.x;
    for (int c = threadIdx.x; c < HID; c += 256) se[c] = E[t * HID + c];
    __syncthreads();
    float a0 = bias[n], a1 = 0.f;
#pragma unroll 4
    for (int k = 0; k < HID; k += 2) {
        a0 = fmaf(se[k],     W[(long)k * HID + n], a0);
        a1 = fmaf(se[k + 1], W[(long)(k + 1) * HID + n], a1);
    }
    O[t * HID + n] = a0 + a1;
}

// ---------------------------------------------------------------------------
// Block reduce for (sum, sumsq) over 256 threads
// ---------------------------------------------------------------------------
__device__ __forceinline__ void block_reduce2(float& s, float& s2, float* red) {
#pragma unroll
    for (int o = 16; o > 0; o >>= 1) {
        s  += __shfl_xor_sync(0xffffffffu, s,  o);
        s2 += __shfl_xor_sync(0xffffffffu, s2, o);
    }
    int warp = threadIdx.x >> 5, lane = threadIdx.x & 31;
    if (lane == 0) { red[warp] = s; red[8 + warp] = s2; }
    __syncthreads();
    if (warp == 0) {
        float a  = (lane < 8) ? red[lane] : 0.f;
        float a2 = (lane < 8) ? red[8 + lane] : 0.f;
#pragma unroll
        for (int o = 4; o > 0; o >>= 1) {
            a  += __shfl_xor_sync(0xffffffffu, a,  o);
            a2 += __shfl_xor_sync(0xffffffffu, a2, o);
        }
        if (lane == 0) { red[16] = a; red[17] = a2; }
    }
    __syncthreads();
    s = red[16]; s2 = red[17];
}

// ---------------------------------------------------------------------------
// LN1: g_x = tf32r( LN( we + per_tag[tag]*mask ) * g + b )
// ---------------------------------------------------------------------------
__global__ void __launch_bounds__(256)
ln1_kernel(const float* __restrict__ we, const int* __restrict__ tags,
           const int* __restrict__ mask,
           const float* __restrict__ g, const float* __restrict__ b) {
    __shared__ float red[18];
    long row = blockIdx.x;
    const float* wr = we + row * HID;
    const float* pr = g_ptag + (long)tags[row] * HID;
    float mk = (float)mask[row];
    int t = threadIdx.x;
    float v[3]; float s = 0.f, s2 = 0.f;
#pragma unroll
    for (int j = 0; j < 3; j++) {
        int c = t + j * 256;
        float val = wr[c] + pr[c] * mk;
        v[j] = val; s += val; s2 += val * val;
    }
    block_reduce2(s, s2, red);
    float mu = s * (1.f / 768.f);
    float var = s2 * (1.f / 768.f) - mu * mu;
    float rs = rsqrtf(var + 1e-12f);
#pragma unroll
    for (int j = 0; j < 3; j++) {
        int c = t + j * 256;
        g_x[row * HID + c] = tf32r((v[j] - mu) * rs * g[c] + b[c]);
    }
}

// ---------------------------------------------------------------------------
// LN2: out = LN(g_ffx) * g + b
// ---------------------------------------------------------------------------
__global__ void __launch_bounds__(256)
ln2_kernel(const float* __restrict__ g, const float* __restrict__ b,
           float* __restrict__ out) {
    __shared__ float red[18];
    long row = blockIdx.x;
    const float* in = g_ffx + row * HID;
    int t = threadIdx.x;
    float v[3]; float s = 0.f, s2 = 0.f;
#pragma unroll
    for (int j = 0; j < 3; j++) {
        int c = t + j * 256;
        float val = in[c];
        v[j] = val; s += val; s2 += val * val;
    }
    block_reduce2(s, s2, red);
    float mu = s * (1.f / 768.f);
    float var = s2 * (1.f / 768.f) - mu * mu;
    float rs = rsqrtf(var + 1e-12f);
#pragma unroll
    for (int j = 0; j < 3; j++) {
        int c = t + j * 256;
        out[row * HID + c] = (v[j] - mu) * rs * g[c] + b[c];
    }
}

// ---------------------------------------------------------------------------
// tf32 mma.sync GEMM: C[M,N] = A[M,K] @ B[K,N]  (+ epilogue)
//   MODE 0: A=g_x,  B=g_w1r, C=g_h,   epi = tf32r(relu(acc + bias))
//   MODE 1: A=g_h,  B=g_w2r, C=g_ffx, epi = acc + bias + g_x (residual)
// CTA tile 128x256, 512 threads (16 warps of 64x32), BK=16,
// 3-stage cp.async pipeline with wait_group<1> (empty-commit tail padding).
// A smem: row-major BK floats/row, 16B chunks XOR-swizzled by ((m>>1)&3).
// B smem: [BK][BN+8] padded rows (bank-conflict-free fragment reads).
// ---------------------------------------------------------------------------
template<int MODE, int N, int K>
__global__ void __launch_bounds__(512, 1)
gemm_kernel(const float* __restrict__ bias) {
    constexpr int BM = 128, BN = 256, BK = 16;
    constexpr int BSTR = BN + 8;               // 264 floats per B row
    constexpr int NS = 3;
    constexpr int ASZ = BM * BK;               // 2048 floats (8 KB)
    constexpr int BSZ = BK * BSTR;             // 4224 floats (16.5 KB)
    constexpr int STG = ASZ + BSZ;             // floats per stage

    extern __shared__ float smem[];            // NS * STG floats

    const float* A = (MODE == 0) ? g_x : g_h;
    const float* B = (MODE == 0) ? g_w1r : g_w2r;
    float* C       = (MODE == 0) ? g_h : g_ffx;

    const int tid = threadIdx.x;
    const int lane = tid & 31;
    const int warp = tid >> 5;
    const int wr = (warp & 1) * 64;            // warp row offset (0/64)
    const int wc = (warp >> 1) * 32;           // warp col offset (0..224)
    const long blockRow = (long)blockIdx.y * BM;
    const int blockCol = blockIdx.x * BN;

    float acc[4][4][4];
#pragma unroll
    for (int mi = 0; mi < 4; mi++)
#pragma unroll
        for (int ni = 0; ni < 4; ni++)
#pragma unroll
            for (int r = 0; r < 4; r++) acc[mi][ni][r] = 0.f;

    const uint32_t sbase = (uint32_t)__cvta_generic_to_shared(smem);

    auto load_tile = [&](int kt, int st) {
        uint32_t sa = sbase + (uint32_t)st * (STG * 4);
        uint32_t sb = sa + ASZ * 4;
        // A: 128 rows x 4 16B-chunks = 512 -> 1 per thread
        {
            int m = tid >> 2, c = tid & 3;
            const float* gp = A + (blockRow + m) * (long)K + kt * BK + c * 4;
            uint32_t so = (uint32_t)(m * BK + ((c ^ ((m >> 1) & 3)) << 2));
            cp_async16(sa + so * 4, gp);
        }
        // B: 16 rows x 64 16B-chunks = 1024 -> 2 per thread
#pragma unroll
        for (int i = 0; i < 2; i++) {
            int idx = tid + i * 512;
            int kk = idx >> 6, cn = idx & 63;
            const float* gp = B + (long)(kt * BK + kk) * N + blockCol + cn * 4;
            uint32_t so = (uint32_t)(kk * BSTR + cn * 4);
            cp_async16(sb + so * 4, gp);
        }
        cp_commit();
    };

    auto compute_tile = [&](int st) {
        const float* a = smem + st * STG;
        const float* bb = smem + st * STG + ASZ;
#pragma unroll
        for (int ks = 0; ks < 2; ks++) {
            const int kk = ks * 8;
            uint32_t af[4][4], bf[4][2];
#pragma unroll
            for (int mi = 0; mi < 4; mi++) {
                int m0 = wr + mi * 16 + (lane >> 2);
                int swz = (m0 >> 1) & 3;
                int base = m0 * BK + (lane & 3);
                int c0 = ((kk >> 2) ^ swz) << 2;
                int c1 = (((kk >> 2) + 1) ^ swz) << 2;
                af[mi][0] = __float_as_uint(a[base + c0]);
                af[mi][1] = __float_as_uint(a[base + c0 + 8 * BK]);
                af[mi][2] = __float_as_uint(a[base + c1]);
                af[mi][3] = __float_as_uint(a[base + c1 + 8 * BK]);
            }
#pragma unroll
            for (int ni = 0; ni < 4; ni++) {
                int off = (kk + (lane & 3)) * BSTR + wc + ni * 8 + (lane >> 2);
                bf[ni][0] = __float_as_uint(bb[off]);
                bf[ni][1] = __float_as_uint(bb[off + 4 * BSTR]);
            }
#pragma unroll
            for (int mi = 0; mi < 4; mi++)
#pragma unroll
                for (int ni = 0; ni < 4; ni++)
                    mma_tf32(acc[mi][ni], af[mi], bf[ni]);
        }
    };

    const int kTiles = K / BK;                 // 48 or 192
    load_tile(0, 0);
    load_tile(1, 1);
    for (int t = 0; t < kTiles; t++) {
        cp_wait<1>();                          // tile t resident (t+1 may pend)
        __syncthreads();                       // all warps done with tile t-1 too
        if (t + 2 < kTiles) load_tile(t + 2, (t + 2) % NS);  // stage (t-1)%NS: safe
        else cp_commit();                      // empty group keeps wait<1> math exact
        compute_tile(t % NS);
    }

    // Epilogue
#pragma unroll
    for (int mi = 0; mi < 4; mi++) {
#pragma unroll
        for (int ri = 0; ri < 2; ri++) {
            long row = blockRow + wr + mi * 16 + (lane >> 2) + ri * 8;
#pragma unroll
            for (int ni = 0; ni < 4; ni++) {
                int col = blockCol + wc + ni * 8 + (lane & 3) * 2;
                float v0 = acc[mi][ni][ri * 2 + 0] + bias[col];
                float v1 = acc[mi][ni][ri * 2 + 1] + bias[col + 1];
                if (MODE == 0) {
                    v0 = tf32r(fmaxf(v0, 0.f));
                    v1 = tf32r(fmaxf(v1, 0.f));
                } else {
                    const float2 r2 = *(const float2*)(g_x + row * N + col);
                    v0 += r2.x; v1 += r2.y;
                }
                float2 o; o.x = v0; o.y = v1;
                *(float2*)(C + row * (long)N + col) = o;
            }
        }
    }
}

// ---------------------------------------------------------------------------
// Launch
// ---------------------------------------------------------------------------
extern "C" void kernel_launch(void* const* d_in, const int* in_sizes, int n_in,
                              void* d_out, int out_size) {
    const float* we      = (const float*)d_in[0];
    const int*   tags    = (const int*)d_in[1];
    const int*   mask    = (const int*)d_in[2];
    const float* tag_emb = (const float*)d_in[3];
    const float* Wv      = (const float*)d_in[4];
    const float* bv      = (const float*)d_in[5];
    const float* Wo      = (const float*)d_in[6];
    const float* bo      = (const float*)d_in[7];
    const float* ln1g    = (const float*)d_in[8];
    const float* ln1b    = (const float*)d_in[9];
    const float* W1      = (const float*)d_in[10];
    const float* b1      = (const float*)d_in[11];
    const float* W2      = (const float*)d_in[12];
    const float* b2      = (const float*)d_in[13];
    const float* ln2g    = (const float*)d_in[14];
    const float* ln2b    = (const float*)d_in[15];
    float* out = (float*)d_out;

    // 3 stages * (8 KB A + 16.5 KB B) = 75264 bytes dynamic smem
    const int smem_bytes = 3 * (128 * 16 + 16 * 264) * 4;
    cudaFuncSetAttribute(gemm_kernel<0, INTR, HID>,
                         cudaFuncAttributeMaxDynamicSharedMemorySize, smem_bytes);
    cudaFuncSetAttribute(gemm_kernel<1, HID, INTR>,
                         cudaFuncAttributeMaxDynamicSharedMemorySize, smem_bytes);

    const int nw = HID * INTR;
    round_w_kernel<0><<<(nw + 255) / 256, 256>>>(W1);
    round_w_kernel<1><<<(nw + 255) / 256, 256>>>(W2);

    tag_gemm_kernel<0><<<dim3(NTAGS, HID / 256), 256>>>(tag_emb, Wv, bv);
    tag_gemm_kernel<1><<<dim3(NTAGS, HID / 256), 256>>>(nullptr, Wo, bo);

    ln1_kernel<<<TOKENS, 256>>>(we, tags, mask, ln1g, ln1b);

    // GEMM1: [32768,768] @ [768,3072], relu+bias, tf32-rounded store
    gemm_kernel<0, INTR, HID>
        <<<dim3(INTR / 256, TOKENS / 128), 512, smem_bytes>>>(b1);

    // GEMM2: [32768,3072] @ [3072,768], bias + residual(g_x)
    gemm_kernel<1, HID, INTR>
        <<<dim3(HID / 256, TOKENS / 128), 512, smem_bytes>>>(b2);

    ln2_kernel<<<TOKENS, 256>>>(ln2g, ln2b, out);
}

// round 7
// speedup vs baseline: 1.4299x; 1.4299x over previous
#include <cuda_runtime.h>
#include <cuda_fp16.h>
#include <cstdint>

#define TOKENS 32768
#define HID 768
#define INTR 3072
#define NTAGS 64

// ---------------------------------------------------------------------------
// Scratch (static device memory — allocation-free per harness rules)
// ---------------------------------------------------------------------------
__device__ __align__(256) __half g_x[(size_t)TOKENS * HID];    // LN1 out (fp16)
__device__ __align__(256) __half g_h[(size_t)TOKENS * INTR];   // relu(x@W1+b1) fp16
__device__ __align__(256) float  g_ffx[(size_t)TOKENS * HID];  // ff + x (fp32)
__device__ __align__(256) __half g_w1t[(size_t)INTR * HID];    // W1^T [n][k] fp16
__device__ __align__(256) __half g_w2t[(size_t)HID * INTR];    // W2^T [n][k] fp16
__device__ __align__(256) float  g_tmp[NTAGS * HID];           // tag_emb@Wv+bv
__device__ __align__(256) float  g_ptag[NTAGS * HID];          // per-tag vector

// ---------------------------------------------------------------------------
// Helpers
// ---------------------------------------------------------------------------
__device__ __forceinline__ void cp_async16(uint32_t saddr, const void* gaddr) {
    asm volatile("cp.async.cg.shared.global [%0], [%1], 16;" :: "r"(saddr), "l"(gaddr));
}
__device__ __forceinline__ void cp_commit() { asm volatile("cp.async.commit_group;"); }
template<int N> __device__ __forceinline__ void cp_wait() {
    asm volatile("cp.async.wait_group %0;" :: "n"(N));
}

__device__ __forceinline__ void mma_f16(float c[4], const uint32_t a[4], const uint32_t b[2]) {
    asm volatile(
        "mma.sync.aligned.m16n8k16.row.col.f32.f16.f16.f32 "
        "{%0,%1,%2,%3}, {%4,%5,%6,%7}, {%8,%9}, {%0,%1,%2,%3};"
        : "+f"(c[0]), "+f"(c[1]), "+f"(c[2]), "+f"(c[3])
        : "r"(a[0]), "r"(a[1]), "r"(a[2]), "r"(a[3]), "r"(b[0]), "r"(b[1]));
}

// ---------------------------------------------------------------------------
// Fused prep kernel:
//   blocks [0, TB)         : transpose+round W -> g_w{1,2}t (half, [n][k])
//   blocks [TB, TB+192)    : tag GEMV stage (64 tags x 3 col chunks)
// WHICH 0: W=W1 [768,3072] -> g_w1t;  tag: g_tmp  = tag_emb@Wv+bv
// WHICH 1: W=W2 [3072,768] -> g_w2t;  tag: g_ptag = g_tmp@Wo+bo
// ---------------------------------------------------------------------------
template<int WHICH, int K, int N>
__global__ void __launch_bounds__(256)
prep_kernel(const float* __restrict__ W,
            const float* __restrict__ E,        // tag emb source (WHICH0 only)
            const float* __restrict__ Wt,       // tag weight (Wv or Wo)
            const float* __restrict__ bt) {     // tag bias (bv or bo)
    __shared__ float sbuf[32 * 33];             // transpose tile / tag se union
    constexpr int TB = (N / 32) * (K / 32);     // 2304 for both shapes
    const int tid = threadIdx.x;
    const int bid = blockIdx.x;

    if (bid < TB) {
        // ---- transpose + fp16 round ----
        int nb = bid % (N / 32), kb = bid / (N / 32);
        int tx = tid & 31, ty = tid >> 5;
        float (*tile)[33] = (float(*)[33])sbuf;
#pragma unroll
        for (int i = ty; i < 32; i += 8)
            tile[i][tx] = W[(long)(kb * 32 + i) * N + nb * 32 + tx];
        __syncthreads();
        __half* out = WHICH ? g_w2t : g_w1t;
#pragma unroll
        for (int i = ty; i < 32; i += 8)
            out[(long)(nb * 32 + i) * K + kb * 32 + tx] = __float2half_rn(tile[tx][i]);
    } else {
        // ---- tag GEMV: O[t][n] = sum_k Es[t][k]*Wt[k][n] + bt[n] ----
        int b2 = bid - TB;
        int t = b2 / 3, chunk = b2 - t * 3;
        int n = chunk * 256 + tid;
        const float* Es = WHICH ? g_tmp : E;
        float* O = WHICH ? g_ptag : g_tmp;
        for (int c = tid; c < HID; c += 256) sbuf[c] = Es[t * HID + c];
        __syncthreads();
        float a0 = bt[n], a1 = 0.f, a2 = 0.f, a3 = 0.f;
        for (int k = 0; k < HID; k += 8) {
            float w0 = Wt[(long)(k + 0) * HID + n];
            float w1 = Wt[(long)(k + 1) * HID + n];
            float w2 = Wt[(long)(k + 2) * HID + n];
            float w3 = Wt[(long)(k + 3) * HID + n];
            float w4 = Wt[(long)(k + 4) * HID + n];
            float w5 = Wt[(long)(k + 5) * HID + n];
            float w6 = Wt[(long)(k + 6) * HID + n];
            float w7 = Wt[(long)(k + 7) * HID + n];
            a0 = fmaf(sbuf[k + 0], w0, a0);
            a1 = fmaf(sbuf[k + 1], w1, a1);
            a2 = fmaf(sbuf[k + 2], w2, a2);
            a3 = fmaf(sbuf[k + 3], w3, a3);
            a0 = fmaf(sbuf[k + 4], w4, a0);
            a1 = fmaf(sbuf[k + 5], w5, a1);
            a2 = fmaf(sbuf[k + 6], w6, a2);
            a3 = fmaf(sbuf[k + 7], w7, a3);
        }
        O[t * HID + n] = (a0 + a1) + (a2 + a3);
    }
}

// ---------------------------------------------------------------------------
// Block reduce for (sum, sumsq) over 256 threads
// ---------------------------------------------------------------------------
__device__ __forceinline__ void block_reduce2(float& s, float& s2, float* red) {
#pragma unroll
    for (int o = 16; o > 0; o >>= 1) {
        s  += __shfl_xor_sync(0xffffffffu, s,  o);
        s2 += __shfl_xor_sync(0xffffffffu, s2, o);
    }
    int warp = threadIdx.x >> 5, lane = threadIdx.x & 31;
    if (lane == 0) { red[warp] = s; red[8 + warp] = s2; }
    __syncthreads();
    if (warp == 0) {
        float a  = (lane < 8) ? red[lane] : 0.f;
        float a2 = (lane < 8) ? red[8 + lane] : 0.f;
#pragma unroll
        for (int o = 4; o > 0; o >>= 1) {
            a  += __shfl_xor_sync(0xffffffffu, a,  o);
            a2 += __shfl_xor_sync(0xffffffffu, a2, o);
        }
        if (lane == 0) { red[16] = a; red[17] = a2; }
    }
    __syncthreads();
    s = red[16]; s2 = red[17];
}

// ---------------------------------------------------------------------------
// LN1: g_x = fp16_rn( LN( we + per_tag[tag]*mask ) * g + b )
// ---------------------------------------------------------------------------
__global__ void __launch_bounds__(256)
ln1_kernel(const float* __restrict__ we, const int* __restrict__ tags,
           const int* __restrict__ mask,
           const float* __restrict__ g, const float* __restrict__ b) {
    __shared__ float red[18];
    long row = blockIdx.x;
    const float* wr = we + row * HID;
    const float* pr = g_ptag + (long)tags[row] * HID;
    float mk = (float)mask[row];
    int t = threadIdx.x;
    float v[3]; float s = 0.f, s2 = 0.f;
#pragma unroll
    for (int j = 0; j < 3; j++) {
        int c = t + j * 256;
        float val = wr[c] + pr[c] * mk;
        v[j] = val; s += val; s2 += val * val;
    }
    block_reduce2(s, s2, red);
    float mu = s * (1.f / 768.f);
    float var = s2 * (1.f / 768.f) - mu * mu;
    float rs = rsqrtf(var + 1e-12f);
#pragma unroll
    for (int j = 0; j < 3; j++) {
        int c = t + j * 256;
        g_x[row * HID + c] = __float2half_rn((v[j] - mu) * rs * g[c] + b[c]);
    }
}

// ---------------------------------------------------------------------------
// LN2: out = LN(g_ffx) * g + b
// ---------------------------------------------------------------------------
__global__ void __launch_bounds__(256)
ln2_kernel(const float* __restrict__ g, const float* __restrict__ b,
           float* __restrict__ out) {
    __shared__ float red[18];
    long row = blockIdx.x;
    const float* in = g_ffx + row * HID;
    int t = threadIdx.x;
    float v[3]; float s = 0.f, s2 = 0.f;
#pragma unroll
    for (int j = 0; j < 3; j++) {
        int c = t + j * 256;
        float val = in[c];
        v[j] = val; s += val; s2 += val * val;
    }
    block_reduce2(s, s2, red);
    float mu = s * (1.f / 768.f);
    float var = s2 * (1.f / 768.f) - mu * mu;
    float rs = rsqrtf(var + 1e-12f);
#pragma unroll
    for (int j = 0; j < 3; j++) {
        int c = t + j * 256;
        out[row * HID + c] = (v[j] - mu) * rs * g[c] + b[c];
    }
}

// ---------------------------------------------------------------------------
// fp16 mma.sync GEMM: C[M,N] = A[M,K(half)] @ Bt[N,K(half)]^T  (+ epilogue)
//   MODE 0: A=g_x,  Bt=g_w1t, C=g_h   (half), epi = fp16_rn(relu(acc+bias))
//   MODE 1: A=g_h,  Bt=g_w2t, C=g_ffx (fp32), epi = acc+bias+float(g_x)
// Tile 128x128, 256 threads (8 warps of 64x32), BK=64 halves (128B rows),
// SW128-style XOR swizzle, 3-stage cp.async pipeline wait_group<1>,
// __launch_bounds__(256,2) -> 2 CTAs/SM (latency cover).
// ---------------------------------------------------------------------------
template<int MODE, int N, int K>
__global__ void __launch_bounds__(256, 2)
hgemm_kernel(const float* __restrict__ bias) {
    constexpr int BM = 128, BN = 128, BK = 64;   // BK in halves; 128 B per row
    constexpr int NS = 3;
    constexpr int ABYTES = BM * BK * 2;          // 16 KB
    constexpr int STG = 2 * ABYTES;              // A + B = 32 KB per stage

    extern __shared__ __align__(16) char smem_raw[];   // NS * STG

    const __half* A  = MODE ? g_h   : g_x;
    const __half* Bt = MODE ? g_w2t : g_w1t;

    const int tid = threadIdx.x;
    const int lane = tid & 31;
    const int warp = tid >> 5;
    const int wr = (warp & 1) * 64;              // warp row (0/64)
    const int wc = (warp >> 1) * 32;             // warp col (0..96)
    const long blockRow = (long)blockIdx.y * BM;
    const int  blockCol = blockIdx.x * BN;

    float acc[4][4][4];
#pragma unroll
    for (int mi = 0; mi < 4; mi++)
#pragma unroll
        for (int ni = 0; ni < 4; ni++)
#pragma unroll
            for (int r = 0; r < 4; r++) acc[mi][ni][r] = 0.f;

    const uint32_t sbase = (uint32_t)__cvta_generic_to_shared(smem_raw);

    // 16B chunk at (row r, chunk c) -> swizzled offset within tile
    auto load_tile = [&](int kt, int st) {
        uint32_t base = sbase + (uint32_t)st * STG;
        // A: 128 rows x 8 chunks = 1024 -> 4/thread
#pragma unroll
        for (int i = 0; i < 4; i++) {
            int idx = tid + i * 256;
            int r = idx >> 3, c = idx & 7;
            const __half* gp = A + (blockRow + r) * (long)K + kt * BK + c * 8;
            cp_async16(base + (uint32_t)(r * 128 + ((c ^ (r & 7)) << 4)), gp);
        }
        // B: 128 n-rows x 8 chunks = 1024 -> 4/thread
#pragma unroll
        for (int i = 0; i < 4; i++) {
            int idx = tid + i * 256;
            int r = idx >> 3, c = idx & 7;
            const __half* gp = Bt + (long)(blockCol + r) * K + kt * BK + c * 8;
            cp_async16(base + ABYTES + (uint32_t)(r * 128 + ((c ^ (r & 7)) << 4)), gp);
        }
        cp_commit();
    };

    auto lds32 = [&](const char* tb, int r, int b) -> uint32_t {
        // b = byte offset within 128B row (multiple of 4)
        int sb = (((b >> 4) ^ (r & 7)) << 4) | (b & 15);
        return *(const uint32_t*)(tb + r * 128 + sb);
    };

    auto compute_tile = [&](int st) {
        const char* sa = smem_raw + st * STG;
        const char* sb = sa + ABYTES;
#pragma unroll
        for (int s = 0; s < 4; s++) {            // 4 x k16 steps over BK=64
            const int kb = s * 32 + (lane & 3) * 4;   // byte offset of k-pair
            uint32_t af[4][4], bf[4][2];
#pragma unroll
            for (int mi = 0; mi < 4; mi++) {
                int r0 = wr + mi * 16 + (lane >> 2);
                af[mi][0] = lds32(sa, r0,     kb);
                af[mi][1] = lds32(sa, r0 + 8, kb);
                af[mi][2] = lds32(sa, r0,     kb + 16);
                af[mi][3] = lds32(sa, r0 + 8, kb + 16);
            }
#pragma unroll
            for (int ni = 0; ni < 4; ni++) {
                int n0 = wc + ni * 8 + (lane >> 2);
                bf[ni][0] = lds32(sb, n0, kb);
                bf[ni][1] = lds32(sb, n0, kb + 16);
            }
#pragma unroll
            for (int mi = 0; mi < 4; mi++)
#pragma unroll
                for (int ni = 0; ni < 4; ni++)
                    mma_f16(acc[mi][ni], af[mi], bf[ni]);
        }
    };

    const int kTiles = K / BK;                   // 12 or 48
    load_tile(0, 0);
    load_tile(1, 1);
    for (int t = 0; t < kTiles; t++) {
        cp_wait<1>();                            // tile t resident
        __syncthreads();
        if (t + 2 < kTiles) load_tile(t + 2, (t + 2) % NS);
        else cp_commit();                        // keep group arithmetic exact
        compute_tile(t % NS);
    }

    // ---- Epilogue ----
#pragma unroll
    for (int mi = 0; mi < 4; mi++) {
#pragma unroll
        for (int ri = 0; ri < 2; ri++) {
            long row = blockRow + wr + mi * 16 + (lane >> 2) + ri * 8;
#pragma unroll
            for (int ni = 0; ni < 4; ni++) {
                int col = blockCol + wc + ni * 8 + (lane & 3) * 2;
                float v0 = acc[mi][ni][ri * 2 + 0] + bias[col];
                float v1 = acc[mi][ni][ri * 2 + 1] + bias[col + 1];
                if (MODE == 0) {
                    __half2 h2;
                    h2.x = __float2half_rn(fmaxf(v0, 0.f));
                    h2.y = __float2half_rn(fmaxf(v1, 0.f));
                    *(__half2*)(g_h + row * (long)N + col) = h2;
                } else {
                    __half2 x2 = *(const __half2*)(g_x + row * HID + col);
                    float2 o;
                    o.x = v0 + __half2float(x2.x);
                    o.y = v1 + __half2float(x2.y);
                    *(float2*)(g_ffx + row * (long)N + col) = o;
                }
            }
        }
    }
}

// ---------------------------------------------------------------------------
// Launch  (order: prep0, prep1, ln1, gemm1 <- ncu-captured slot, gemm2, ln2)
// ---------------------------------------------------------------------------
extern "C" void kernel_launch(void* const* d_in, const int* in_sizes, int n_in,
                              void* d_out, int out_size) {
    const float* we      = (const float*)d_in[0];
    const int*   tags    = (const int*)d_in[1];
    const int*   mask    = (const int*)d_in[2];
    const float* tag_emb = (const float*)d_in[3];
    const float* Wv      = (const float*)d_in[4];
    const float* bv      = (const float*)d_in[5];
    const float* Wo      = (const float*)d_in[6];
    const float* bo      = (const float*)d_in[7];
    const float* ln1g    = (const float*)d_in[8];
    const float* ln1b    = (const float*)d_in[9];
    const float* W1      = (const float*)d_in[10];
    const float* b1      = (const float*)d_in[11];
    const float* W2      = (const float*)d_in[12];
    const float* b2      = (const float*)d_in[13];
    const float* ln2g    = (const float*)d_in[14];
    const float* ln2b    = (const float*)d_in[15];
    float* out = (float*)d_out;

    const int smem_bytes = 3 * 2 * 128 * 64 * 2;   // 98304 B
    cudaFuncSetAttribute(hgemm_kernel<0, INTR, HID>,
                         cudaFuncAttributeMaxDynamicSharedMemorySize, smem_bytes);
    cudaFuncSetAttribute(hgemm_kernel<1, HID, INTR>,
                         cudaFuncAttributeMaxDynamicSharedMemorySize, smem_bytes);

    // prep0: transpose W1 -> g_w1t (2304 blocks) + tag stage 0 (192 blocks)
    prep_kernel<0, HID, INTR><<<2304 + 192, 256>>>(W1, tag_emb, Wv, bv);
    // prep1: transpose W2 -> g_w2t + tag stage 1
    prep_kernel<1, INTR, HID><<<2304 + 192, 256>>>(W2, nullptr, Wo, bo);

    ln1_kernel<<<TOKENS, 256>>>(we, tags, mask, ln1g, ln1b);

    // GEMM1: [32768,768] @ [768,3072] fp16 HMMA, relu+bias -> g_h (half)
    hgemm_kernel<0, INTR, HID>
        <<<dim3(INTR / 128, TOKENS / 128), 256, smem_bytes>>>(b1);

    // GEMM2: [32768,3072] @ [3072,768] fp16 HMMA, bias + residual -> g_ffx
    hgemm_kernel<1, HID, INTR>
        <<<dim3(HID / 128, TOKENS / 128), 256, smem_bytes>>>(b2);

    ln2_kernel<<<TOKENS, 256>>>(ln2g, ln2b, out);
}

// round 8
// speedup vs baseline: 2.5874x; 1.8095x over previous
#include <cuda_runtime.h>
#include <cuda_fp16.h>
#include <cstdint>

#define TOKENS 32768
#define HID 768
#define INTR 3072
#define NTAGS 64

// ---------------------------------------------------------------------------
// Scratch (static device memory — allocation-free per harness rules)
// ---------------------------------------------------------------------------
__device__ __align__(256) __half g_x[(size_t)TOKENS * HID];    // LN1 out (fp16)
__device__ __align__(256) __half g_h[(size_t)TOKENS * INTR];   // relu(x@W1+b1) fp16
__device__ __align__(256) float  g_ffx[(size_t)TOKENS * HID];  // ff + x (fp32)
__device__ __align__(256) __half g_w1t[(size_t)INTR * HID];    // W1^T [n][k] fp16
__device__ __align__(256) __half g_w2t[(size_t)HID * INTR];    // W2^T [n][k] fp16
__device__ __align__(256) float  g_tmp[NTAGS * HID];           // tag_emb@Wv+bv
__device__ __align__(256) float  g_ptag[NTAGS * HID];          // per-tag vector

// ---------------------------------------------------------------------------
// Helpers
// ---------------------------------------------------------------------------
__device__ __forceinline__ void cp_async16(uint32_t saddr, const void* gaddr) {
    asm volatile("cp.async.cg.shared.global [%0], [%1], 16;" :: "r"(saddr), "l"(gaddr));
}
__device__ __forceinline__ void cp_commit() { asm volatile("cp.async.commit_group;"); }
template<int N> __device__ __forceinline__ void cp_wait() {
    asm volatile("cp.async.wait_group %0;" :: "n"(N));
}

__device__ __forceinline__ void mma_f16(float c[4], const uint32_t a[4],
                                        uint32_t b0, uint32_t b1) {
    asm volatile(
        "mma.sync.aligned.m16n8k16.row.col.f32.f16.f16.f32 "
        "{%0,%1,%2,%3}, {%4,%5,%6,%7}, {%8,%9}, {%0,%1,%2,%3};"
        : "+f"(c[0]), "+f"(c[1]), "+f"(c[2]), "+f"(c[3])
        : "r"(a[0]), "r"(a[1]), "r"(a[2]), "r"(a[3]), "r"(b0), "r"(b1));
}

__device__ __forceinline__ void ldsm_x4(uint32_t r[4], uint32_t addr) {
    asm volatile("ldmatrix.sync.aligned.m8n8.x4.shared.b16 {%0,%1,%2,%3}, [%4];"
        : "=r"(r[0]), "=r"(r[1]), "=r"(r[2]), "=r"(r[3]) : "r"(addr));
}

// ---------------------------------------------------------------------------
// Fused prep kernel:
//   blocks [0, TB)         : transpose+round W -> g_w{1,2}t (half, [n][k])
//   blocks [TB, TB+192)    : tag GEMV stage (64 tags x 3 col chunks)
// ---------------------------------------------------------------------------
template<int WHICH, int K, int N>
__global__ void __launch_bounds__(256)
prep_kernel(const float* __restrict__ W,
            const float* __restrict__ E,
            const float* __restrict__ Wt,
            const float* __restrict__ bt) {
    __shared__ float sbuf[32 * 33];
    constexpr int TB = (N / 32) * (K / 32);
    const int tid = threadIdx.x;
    const int bid = blockIdx.x;

    if (bid < TB) {
        int nb = bid % (N / 32), kb = bid / (N / 32);
        int tx = tid & 31, ty = tid >> 5;
        float (*tile)[33] = (float(*)[33])sbuf;
#pragma unroll
        for (int i = ty; i < 32; i += 8)
            tile[i][tx] = W[(long)(kb * 32 + i) * N + nb * 32 + tx];
        __syncthreads();
        __half* out = WHICH ? g_w2t : g_w1t;
#pragma unroll
        for (int i = ty; i < 32; i += 8)
            out[(long)(nb * 32 + i) * K + kb * 32 + tx] = __float2half_rn(tile[tx][i]);
    } else {
        int b2 = bid - TB;
        int t = b2 / 3, chunk = b2 - t * 3;
        int n = chunk * 256 + tid;
        const float* Es = WHICH ? g_tmp : E;
        float* O = WHICH ? g_ptag : g_tmp;
        for (int c = tid; c < HID; c += 256) sbuf[c] = Es[t * HID + c];
        __syncthreads();
        float a0 = bt[n], a1 = 0.f, a2 = 0.f, a3 = 0.f;
        for (int k = 0; k < HID; k += 8) {
            float w0 = Wt[(long)(k + 0) * HID + n];
            float w1 = Wt[(long)(k + 1) * HID + n];
            float w2 = Wt[(long)(k + 2) * HID + n];
            float w3 = Wt[(long)(k + 3) * HID + n];
            float w4 = Wt[(long)(k + 4) * HID + n];
            float w5 = Wt[(long)(k + 5) * HID + n];
            float w6 = Wt[(long)(k + 6) * HID + n];
            float w7 = Wt[(long)(k + 7) * HID + n];
            a0 = fmaf(sbuf[k + 0], w0, a0);
            a1 = fmaf(sbuf[k + 1], w1, a1);
            a2 = fmaf(sbuf[k + 2], w2, a2);
            a3 = fmaf(sbuf[k + 3], w3, a3);
            a0 = fmaf(sbuf[k + 4], w4, a0);
            a1 = fmaf(sbuf[k + 5], w5, a1);
            a2 = fmaf(sbuf[k + 6], w6, a2);
            a3 = fmaf(sbuf[k + 7], w7, a3);
        }
        O[t * HID + n] = (a0 + a1) + (a2 + a3);
    }
}

// ---------------------------------------------------------------------------
// Block reduce for (sum, sumsq) over 256 threads
// ---------------------------------------------------------------------------
__device__ __forceinline__ void block_reduce2(float& s, float& s2, float* red) {
#pragma unroll
    for (int o = 16; o > 0; o >>= 1) {
        s  += __shfl_xor_sync(0xffffffffu, s,  o);
        s2 += __shfl_xor_sync(0xffffffffu, s2, o);
    }
    int warp = threadIdx.x >> 5, lane = threadIdx.x & 31;
    if (lane == 0) { red[warp] = s; red[8 + warp] = s2; }
    __syncthreads();
    if (warp == 0) {
        float a  = (lane < 8) ? red[lane] : 0.f;
        float a2 = (lane < 8) ? red[8 + lane] : 0.f;
#pragma unroll
        for (int o = 4; o > 0; o >>= 1) {
            a  += __shfl_xor_sync(0xffffffffu, a,  o);
            a2 += __shfl_xor_sync(0xffffffffu, a2, o);
        }
        if (lane == 0) { red[16] = a; red[17] = a2; }
    }
    __syncthreads();
    s = red[16]; s2 = red[17];
}

// ---------------------------------------------------------------------------
// LN1: g_x = fp16_rn( LN( we + per_tag[tag]*mask ) * g + b )
// ---------------------------------------------------------------------------
__global__ void __launch_bounds__(256)
ln1_kernel(const float* __restrict__ we, const int* __restrict__ tags,
           const int* __restrict__ mask,
           const float* __restrict__ g, const float* __restrict__ b) {
    __shared__ float red[18];
    long row = blockIdx.x;
    const float* wr = we + row * HID;
    const float* pr = g_ptag + (long)tags[row] * HID;
    float mk = (float)mask[row];
    int t = threadIdx.x;
    float v[3]; float s = 0.f, s2 = 0.f;
#pragma unroll
    for (int j = 0; j < 3; j++) {
        int c = t + j * 256;
        float val = wr[c] + pr[c] * mk;
        v[j] = val; s += val; s2 += val * val;
    }
    block_reduce2(s, s2, red);
    float mu = s * (1.f / 768.f);
    float var = s2 * (1.f / 768.f) - mu * mu;
    float rs = rsqrtf(var + 1e-12f);
#pragma unroll
    for (int j = 0; j < 3; j++) {
        int c = t + j * 256;
        g_x[row * HID + c] = __float2half_rn((v[j] - mu) * rs * g[c] + b[c]);
    }
}

// ---------------------------------------------------------------------------
// LN2: out = LN(g_ffx) * g + b
// ---------------------------------------------------------------------------
__global__ void __launch_bounds__(256)
ln2_kernel(const float* __restrict__ g, const float* __restrict__ b,
           float* __restrict__ out) {
    __shared__ float red[18];
    long row = blockIdx.x;
    const float* in = g_ffx + row * HID;
    int t = threadIdx.x;
    float v[3]; float s = 0.f, s2 = 0.f;
#pragma unroll
    for (int j = 0; j < 3; j++) {
        int c = t + j * 256;
        float val = in[c];
        v[j] = val; s += val; s2 += val * val;
    }
    block_reduce2(s, s2, red);
    float mu = s * (1.f / 768.f);
    float var = s2 * (1.f / 768.f) - mu * mu;
    float rs = rsqrtf(var + 1e-12f);
#pragma unroll
    for (int j = 0; j < 3; j++) {
        int c = t + j * 256;
        out[row * HID + c] = (v[j] - mu) * rs * g[c] + b[c];
    }
}

// ---------------------------------------------------------------------------
// fp16 mma.sync GEMM with ldmatrix fragment loads.
//   MODE 0: A=g_x,  Bt=g_w1t, C=g_h   (half), epi = fp16_rn(relu(acc+bias))
//   MODE 1: A=g_h,  Bt=g_w2t, C=g_ffx (fp32), epi = acc+bias+float(g_x)
// Tile 128x128, 256 threads (8 warps of 64x32), BK=64 halves (128B rows),
// XOR swizzle (chunk ^ (row&7)), 3-stage cp.async, wait_group<1>, 2 CTAs/SM.
// ---------------------------------------------------------------------------
template<int MODE, int N, int K>
__global__ void __launch_bounds__(256, 2)
hgemm_kernel(const float* __restrict__ bias) {
    constexpr int BM = 128, BN = 128, BK = 64;   // BK in halves; 128 B per row
    constexpr int NS = 3;
    constexpr int ABYTES = BM * BK * 2;          // 16 KB
    constexpr int STG = 2 * ABYTES;              // 32 KB per stage

    extern __shared__ __align__(16) char smem_raw[];

    const __half* A  = MODE ? g_h   : g_x;
    const __half* Bt = MODE ? g_w2t : g_w1t;

    const int tid = threadIdx.x;
    const int lane = tid & 31;
    const int warp = tid >> 5;
    const int wr = (warp & 1) * 64;              // warp row (0/64)
    const int wc = (warp >> 1) * 32;             // warp col (0..96)
    const long blockRow = (long)blockIdx.y * BM;
    const int  blockCol = blockIdx.x * BN;

    float acc[4][4][4];
#pragma unroll
    for (int mi = 0; mi < 4; mi++)
#pragma unroll
        for (int ni = 0; ni < 4; ni++)
#pragma unroll
            for (int r = 0; r < 4; r++) acc[mi][ni][r] = 0.f;

    const uint32_t sbase = (uint32_t)__cvta_generic_to_shared(smem_raw);

    // ldmatrix per-lane row/chunk components (verified vs R7 scalar mapping):
    // A x4: lanes 0-15 rows (l&15), k+0; lanes 16-31 rows (l&15), k+16B.
    const int  rA_lane = wr + (lane & 15);       // + mi*16
    const uint32_t eA = (uint32_t)(lane >> 4);   // extra 16B chunk
    // B x4 (covers n-pair of 16): lanes {0-7,8-15}: rows n0+(l&7) with k+0,k+16;
    //                             lanes {16-23,24-31}: rows n0+8+(l&7) same.
    const int  rB_lane = wc + ((lane & 16) >> 1) + (lane & 7);  // + pair*16
    const uint32_t eB = (uint32_t)((lane >> 3) & 1);

    auto load_tile = [&](int kt, int st) {
        uint32_t base = sbase + (uint32_t)st * STG;
#pragma unroll
        for (int i = 0; i < 4; i++) {
            int idx = tid + i * 256;
            int r = idx >> 3, c = idx & 7;
            const __half* gp = A + (blockRow + r) * (long)K + kt * BK + c * 8;
            cp_async16(base + (uint32_t)(r * 128 + ((c ^ (r & 7)) << 4)), gp);
        }
#pragma unroll
        for (int i = 0; i < 4; i++) {
            int idx = tid + i * 256;
            int r = idx >> 3, c = idx & 7;
            const __half* gp = Bt + (long)(blockCol + r) * K + kt * BK + c * 8;
            cp_async16(base + ABYTES + (uint32_t)(r * 128 + ((c ^ (r & 7)) << 4)), gp);
        }
        cp_commit();
    };

    auto compute_tile = [&](int st) {
        const uint32_t sa = sbase + (uint32_t)st * STG;
        const uint32_t sb = sa + ABYTES;
        // Row-dependent parts (stage-invariant swizzle keys)
        uint32_t aRow[4], aSwz[4], bRow[2], bSwz[2];
#pragma unroll
        for (int mi = 0; mi < 4; mi++) {
            int r = rA_lane + mi * 16;
            aRow[mi] = sa + (uint32_t)(r * 128);
            aSwz[mi] = (uint32_t)(r & 7);
        }
#pragma unroll
        for (int p = 0; p < 2; p++) {
            int r = rB_lane + p * 16;
            bRow[p] = sb + (uint32_t)(r * 128);
            bSwz[p] = (uint32_t)(r & 7);
        }
#pragma unroll
        for (int s = 0; s < 4; s++) {            // 4 x k16 steps over BK=64
            const uint32_t cA = (uint32_t)(s * 2) + eA;   // chunk index for A
            const uint32_t cB = (uint32_t)(s * 2) + eB;   // chunk index for B
            uint32_t af[4][4], bf[2][4];
#pragma unroll
            for (int mi = 0; mi < 4; mi++)
                ldsm_x4(af[mi], aRow[mi] + ((cA ^ aSwz[mi]) << 4));
#pragma unroll
            for (int p = 0; p < 2; p++)
                ldsm_x4(bf[p], bRow[p] + ((cB ^ bSwz[p]) << 4));
#pragma unroll
            for (int mi = 0; mi < 4; mi++) {
#pragma unroll
                for (int p = 0; p < 2; p++) {
                    mma_f16(acc[mi][2 * p + 0], af[mi], bf[p][0], bf[p][1]);
                    mma_f16(acc[mi][2 * p + 1], af[mi], bf[p][2], bf[p][3]);
                }
            }
        }
    };

    const int kTiles = K / BK;                   // 12 or 48
    load_tile(0, 0);
    load_tile(1, 1);
    for (int t = 0; t < kTiles; t++) {
        cp_wait<1>();                            // tile t resident
        __syncthreads();
        if (t + 2 < kTiles) load_tile(t + 2, (t + 2) % NS);
        else cp_commit();                        // keep group arithmetic exact
        compute_tile(t % NS);
    }

    // ---- Epilogue ----
#pragma unroll
    for (int mi = 0; mi < 4; mi++) {
#pragma unroll
        for (int ri = 0; ri < 2; ri++) {
            long row = blockRow + wr + mi * 16 + (lane >> 2) + ri * 8;
#pragma unroll
            for (int ni = 0; ni < 4; ni++) {
                int col = blockCol + wc + ni * 8 + (lane & 3) * 2;
                float v0 = acc[mi][ni][ri * 2 + 0] + bias[col];
                float v1 = acc[mi][ni][ri * 2 + 1] + bias[col + 1];
                if (MODE == 0) {
                    __half2 h2;
                    h2.x = __float2half_rn(fmaxf(v0, 0.f));
                    h2.y = __float2half_rn(fmaxf(v1, 0.f));
                    *(__half2*)(g_h + row * (long)N + col) = h2;
                } else {
                    __half2 x2 = *(const __half2*)(g_x + row * HID + col);
                    float2 o;
                    o.x = v0 + __half2float(x2.x);
                    o.y = v1 + __half2float(x2.y);
                    *(float2*)(g_ffx + row * (long)N + col) = o;
                }
            }
        }
    }
}

// ---------------------------------------------------------------------------
// Launch  (order keeps gemm1 at the ncu-captured slot #4)
// ---------------------------------------------------------------------------
extern "C" void kernel_launch(void* const* d_in, const int* in_sizes, int n_in,
                              void* d_out, int out_size) {
    const float* we      = (const float*)d_in[0];
    const int*   tags    = (const int*)d_in[1];
    const int*   mask    = (const int*)d_in[2];
    const float* tag_emb = (const float*)d_in[3];
    const float* Wv      = (const float*)d_in[4];
    const float* bv      = (const float*)d_in[5];
    const float* Wo      = (const float*)d_in[6];
    const float* bo      = (const float*)d_in[7];
    const float* ln1g    = (const float*)d_in[8];
    const float* ln1b    = (const float*)d_in[9];
    const float* W1      = (const float*)d_in[10];
    const float* b1      = (const float*)d_in[11];
    const float* W2      = (const float*)d_in[12];
    const float* b2      = (const float*)d_in[13];
    const float* ln2g    = (const float*)d_in[14];
    const float* ln2b    = (const float*)d_in[15];
    float* out = (float*)d_out;

    const int smem_bytes = 3 * 2 * 128 * 64 * 2;   // 98304 B
    cudaFuncSetAttribute(hgemm_kernel<0, INTR, HID>,
                         cudaFuncAttributeMaxDynamicSharedMemorySize, smem_bytes);
    cudaFuncSetAttribute(hgemm_kernel<1, HID, INTR>,
                         cudaFuncAttributeMaxDynamicSharedMemorySize, smem_bytes);

    prep_kernel<0, HID, INTR><<<2304 + 192, 256>>>(W1, tag_emb, Wv, bv);
    prep_kernel<1, INTR, HID><<<2304 + 192, 256>>>(W2, nullptr, Wo, bo);

    ln1_kernel<<<TOKENS, 256>>>(we, tags, mask, ln1g, ln1b);

    hgemm_kernel<0, INTR, HID>
        <<<dim3(INTR / 128, TOKENS / 128), 256, smem_bytes>>>(b1);

    hgemm_kernel<1, HID, INTR>
        <<<dim3(HID / 128, TOKENS / 128), 256, smem_bytes>>>(b2);

    ln2_kernel<<<TOKENS, 256>>>(ln2g, ln2b, out);
}